// round 8
// baseline (speedup 1.0000x reference)
#include <cuda_runtime.h>
#include <math.h>

#define BVAL 32
#define TVAL 32
#define SVAL 128
#define HVAL 512
#define EVAL 512
#define VVAL 50257
#define LVAL 2
#define SOS_ID 1

// ---------------- scratch (device globals; no runtime allocation) ----------------
__device__ float g_encproj[SVAL * BVAL * HVAL];        // (s*B+b, H)
__device__ float g_xall[TVAL * BVAL * EVAL];           // (t*B+b, E)
__device__ float g_gx0[TVAL * BVAL * 3 * HVAL];        // (t*B+b, 3H)
__device__ float g_hbuf[2][LVAL * BVAL * HVAL];        // ping-pong hidden state
__device__ float g_ctx[BVAL * HVAL];
__device__ float g_concats[TVAL * BVAL * HVAL];        // (t*B+b, H)

#define FMA2(ACC,A,B) \
    asm("fma.rn.f32x2 %0, %1, %2, %0;" : "+l"(ACC) : "l"(A), "l"(B))
#define PACKDUP(OUT,F) \
    asm("mov.b64 %0, {%1, %1};" : "=l"(OUT) : "r"(__float_as_uint(F)))

// ---------------- small kernels ----------------
__global__ void init_h_kernel(const float* __restrict__ dh) {
    int i = blockIdx.x * blockDim.x + threadIdx.x;
    if (i < LVAL * BVAL * HVAL) g_hbuf[0][i] = dh[i];
}
__global__ void final_h_kernel(float* __restrict__ out) {
    int i = blockIdx.x * blockDim.x + threadIdx.x;
    if (i < LVAL * BVAL * HVAL) out[i] = g_hbuf[0][i];
}
__global__ void embed_kernel(const int* __restrict__ tgt, const float* __restrict__ emb) {
    int row = blockIdx.x;           // t*B + b
    int t = row >> 5, b = row & 31;
    int tok = (t == 0) ? SOS_ID : tgt[b * TVAL + t - 1];
    float4 v = *(const float4*)(emb + (size_t)tok * EVAL + threadIdx.x * 4);
    *(float4*)(g_xall + (size_t)row * EVAL + threadIdx.x * 4) = v;
}

// ---------------- f32x2 SGEMM:  C[M,N] = A[M,K] @ B[N,K]^T + bias[N] ----------------
// R1's proven layout (As/Bs [8][132] k-major tiles, identical load/epilogue
// addressing) + R3's register double-buffered loop + f32x2 inner product:
// A-fragments read as ulonglong2 (pairs over M), B duplicated into both lanes.
// Grid M-fastest. a_sel: 0=param, 1=g_xall, 2=g_concats ; c_sel: 0=param, 1=g_encproj, 2=g_gx0
__global__ __launch_bounds__(256) void sgemm_f2_kernel(
    const float* __restrict__ Ap, const float* __restrict__ Bw,
    const float* __restrict__ bias, float* __restrict__ Cp,
    int M, int N, int K, int a_sel, int c_sel)
{
    const float* A = (a_sel == 0) ? Ap : (a_sel == 1) ? g_xall : g_concats;
    float* C = (c_sel == 0) ? Cp : (c_sel == 1) ? g_encproj : g_gx0;

    __shared__ float As[2][8][132];
    __shared__ float Bs[2][8][132];

    const int tid = threadIdx.x;
    const int warp = tid >> 5, lane = tid & 31;
    const int m0 = blockIdx.x * 128;          // M fastest: M-tiles share B slab
    const int n0 = blockIdx.y * 128;
    const int wm = (warp & 3) * 32;
    const int wn = (warp >> 2) * 64;
    const int tm = wm + (lane >> 3) * 4;
    const int tn = wn + (lane & 7) * 4;

    unsigned long long acc[4][8];
#pragma unroll
    for (int p = 0; p < 4; p++)
#pragma unroll
        for (int j = 0; j < 8; j++) acc[p][j] = 0ull;

    const int lrow = tid >> 1;
    const int lcol = (tid & 1) * 4;
    const float* Ald = A + (size_t)(m0 + lrow) * K + lcol;
    const int gn = n0 + lrow;
    const bool bvalid = gn < N;
    const float* Bld = Bw + (size_t)(bvalid ? gn : 0) * K + lcol;

    float4 av = *(const float4*)Ald;
    float4 bv = make_float4(0.f, 0.f, 0.f, 0.f);
    if (bvalid) bv = *(const float4*)Bld;

    for (int k0 = 0; k0 < K; k0 += 8) {
        const int cur = (k0 >> 3) & 1;
        As[cur][lcol + 0][lrow] = av.x; As[cur][lcol + 1][lrow] = av.y;
        As[cur][lcol + 2][lrow] = av.z; As[cur][lcol + 3][lrow] = av.w;
        Bs[cur][lcol + 0][lrow] = bv.x; Bs[cur][lcol + 1][lrow] = bv.y;
        Bs[cur][lcol + 2][lrow] = bv.z; Bs[cur][lcol + 3][lrow] = bv.w;
        __syncthreads();
        if (k0 + 8 < K) {
            av = *(const float4*)(Ald + k0 + 8);
            if (bvalid) bv = *(const float4*)(Bld + k0 + 8);
        }
#pragma unroll
        for (int k = 0; k < 8; k++) {
            // A pairs over m: (tm,tm+1),(tm+2,tm+3),(tm+16,17),(tm+18,19)
            ulonglong2 a01 = *(const ulonglong2*)&As[cur][k][tm];
            ulonglong2 a23 = *(const ulonglong2*)&As[cur][k][tm + 16];
            float4 b0 = *(const float4*)&Bs[cur][k][tn];
            float4 b1 = *(const float4*)&Bs[cur][k][tn + 32];
            unsigned long long bd[8];
            PACKDUP(bd[0], b0.x); PACKDUP(bd[1], b0.y);
            PACKDUP(bd[2], b0.z); PACKDUP(bd[3], b0.w);
            PACKDUP(bd[4], b1.x); PACKDUP(bd[5], b1.y);
            PACKDUP(bd[6], b1.z); PACKDUP(bd[7], b1.w);
#pragma unroll
            for (int j = 0; j < 8; j++) {
                FMA2(acc[0][j], a01.x, bd[j]);
                FMA2(acc[1][j], a01.y, bd[j]);
                FMA2(acc[2][j], a23.x, bd[j]);
                FMA2(acc[3][j], a23.y, bd[j]);
            }
        }
        __syncthreads();
    }

    // ---- epilogue: same (row,col) set as R1, regrouped into lo/hi pairs ----
#pragma unroll
    for (int p = 0; p < 4; p++) {
        const int mrow = m0 + tm + ((p < 2) ? 2 * p : 12 + 2 * p);
        float* cr0 = C + (size_t)mrow * N;
        float* cr1 = C + (size_t)(mrow + 1) * N;
#pragma unroll
        for (int j = 0; j < 8; j++) {
            const int gc = n0 + tn + ((j < 4) ? j : (28 + j));
            if (gc < N) {
                float2 v = *(float2*)&acc[p][j];
                cr0[gc] = v.x + bias[gc];
                cr1[gc] = v.y + bias[gc];
            }
        }
    }
}

// ---------------- fused GRU step (one layer) ----------------
template <bool HAS_X>
__global__ __launch_bounds__(128) void gru_step_kernel(
    const float* __restrict__ Wih, const float* __restrict__ Whh,
    const float* __restrict__ bih, const float* __restrict__ bhh,
    int t, int layer, int buf_in, int buf_out)
{
    constexpr int PER = HAS_X ? 6 : 3;
    __shared__ float h_s[32][133];
    __shared__ float x_s[HAS_X ? 32 : 1][133];
    __shared__ float w_s[PER * 4][128];

    const int tid = threadIdx.x;
    const int warp = tid >> 5, lane = tid & 31;
    const int j = blockIdx.x * 4 + warp;
    const int b = lane;

    const float* h_in = g_hbuf[buf_in] + layer * BVAL * HVAL;
    const float* x_in = g_hbuf[buf_out];
    float* h_out = g_hbuf[buf_out] + layer * BVAL * HVAL;

    float ar = 0.f, az = 0.f, an = 0.f;
    float xr = 0.f, xz = 0.f, xn = 0.f;

    for (int k0 = 0; k0 < HVAL; k0 += 128) {
#pragma unroll
        for (int it = 0; it < 8; ++it) {
            int flat = tid + it * 128;
            int bb = flat >> 5, kq = flat & 31;
            float4 v = *(const float4*)(h_in + bb * HVAL + k0 + kq * 4);
            h_s[bb][kq * 4 + 0] = v.x; h_s[bb][kq * 4 + 1] = v.y;
            h_s[bb][kq * 4 + 2] = v.z; h_s[bb][kq * 4 + 3] = v.w;
            if (HAS_X) {
                float4 u = *(const float4*)(x_in + bb * HVAL + k0 + kq * 4);
                x_s[bb][kq * 4 + 0] = u.x; x_s[bb][kq * 4 + 1] = u.y;
                x_s[bb][kq * 4 + 2] = u.z; x_s[bb][kq * 4 + 3] = u.w;
            }
        }
#pragma unroll
        for (int it = 0; it < PER; ++it) {
            int flat = tid + it * 128;
            int r = flat >> 5, kq = flat & 31;
            int jl = r / PER, which = r % PER;
            int jj = blockIdx.x * 4 + jl;
            const float* src;
            if (HAS_X)
                src = (which < 3) ? (Wih + ((size_t)(which * HVAL + jj)) * HVAL)
                                  : (Whh + ((size_t)((which - 3) * HVAL + jj)) * HVAL);
            else
                src = Whh + ((size_t)(which * HVAL + jj)) * HVAL;
            float4 w = *(const float4*)(src + k0 + kq * 4);
            w_s[r][kq * 4 + 0] = w.x; w_s[r][kq * 4 + 1] = w.y;
            w_s[r][kq * 4 + 2] = w.z; w_s[r][kq * 4 + 3] = w.w;
        }
        __syncthreads();
        const int wb = warp * PER;
#pragma unroll 4
        for (int k = 0; k < 128; k++) {
            float hv = h_s[b][k];
            if (HAS_X) {
                float xv = x_s[b][k];
                xr = fmaf(w_s[wb + 0][k], xv, xr);
                xz = fmaf(w_s[wb + 1][k], xv, xz);
                xn = fmaf(w_s[wb + 2][k], xv, xn);
                ar = fmaf(w_s[wb + 3][k], hv, ar);
                az = fmaf(w_s[wb + 4][k], hv, az);
                an = fmaf(w_s[wb + 5][k], hv, an);
            } else {
                ar = fmaf(w_s[wb + 0][k], hv, ar);
                az = fmaf(w_s[wb + 1][k], hv, az);
                an = fmaf(w_s[wb + 2][k], hv, an);
            }
        }
        __syncthreads();
    }

    float gxr, gxz, gxn;
    if (HAS_X) {
        gxr = xr + bih[j]; gxz = xz + bih[HVAL + j]; gxn = xn + bih[2 * HVAL + j];
    } else {
        const float* g = g_gx0 + ((size_t)(t * BVAL + b)) * 3 * HVAL;
        gxr = g[j]; gxz = g[HVAL + j]; gxn = g[2 * HVAL + j];
    }
    float ghr = ar + bhh[j];
    float ghz = az + bhh[HVAL + j];
    float ghn = an + bhh[2 * HVAL + j];
    float rg = 1.f / (1.f + __expf(-(gxr + ghr)));
    float zg = 1.f / (1.f + __expf(-(gxz + ghz)));
    float ng = tanhf(gxn + rg * ghn);
    h_out[b * HVAL + j] = (1.f - zg) * ng + zg * h_in[b * HVAL + j];
}

// ---------------- attention ----------------
__global__ __launch_bounds__(128) void attn_kernel(
    const float* __restrict__ enc, const unsigned char* __restrict__ mask, int hb)
{
    const int b = blockIdx.x;
    const int tid = threadIdx.x;
    const int warp = tid >> 5, lane = tid & 31;
    const float* h1 = g_hbuf[hb] + BVAL * HVAL;

    __shared__ float hs[HVAL];
    __shared__ float sc[SVAL];
    __shared__ float red[4];

    ((float4*)hs)[tid] = *(const float4*)(h1 + b * HVAL + tid * 4);
    __syncthreads();

    for (int s = warp; s < SVAL; s += 4) {
        const float* ep = g_encproj + ((size_t)(s * BVAL + b)) * HVAL;
        float p = 0.f;
#pragma unroll 4
        for (int k = lane; k < HVAL; k += 32) p = fmaf(hs[k], ep[k], p);
#pragma unroll
        for (int o = 16; o > 0; o >>= 1) p += __shfl_down_sync(0xffffffffu, p, o);
        if (lane == 0) sc[s] = mask[b * SVAL + s] ? -1e9f : p;
    }
    __syncthreads();

    float v = sc[tid];
    float m = v;
#pragma unroll
    for (int o = 16; o > 0; o >>= 1) m = fmaxf(m, __shfl_xor_sync(0xffffffffu, m, o));
    if (lane == 0) red[warp] = m;
    __syncthreads();
    m = fmaxf(fmaxf(red[0], red[1]), fmaxf(red[2], red[3]));
    __syncthreads();
    float e = __expf(v - m);
    float s = e;
#pragma unroll
    for (int o = 16; o > 0; o >>= 1) s += __shfl_xor_sync(0xffffffffu, s, o);
    if (lane == 0) red[warp] = s;
    __syncthreads();
    s = red[0] + red[1] + red[2] + red[3];
    sc[tid] = e / s;
    __syncthreads();

    for (int hh = tid; hh < HVAL; hh += 128) {
        float acc = 0.f;
#pragma unroll 4
        for (int ss = 0; ss < SVAL; ss++)
            acc = fmaf(sc[ss], enc[((size_t)(ss * BVAL + b)) * HVAL + hh], acc);
        g_ctx[b * HVAL + hh] = acc;
    }
}

// ---------------- concat projection ----------------
__global__ __launch_bounds__(128) void concat_kernel(
    const float* __restrict__ Wc, const float* __restrict__ bc, int t, int hb)
{
    __shared__ float c_s[32][133];
    __shared__ float w_s[4][128];
    const int tid = threadIdx.x;
    const int warp = tid >> 5, lane = tid & 31;
    const int j = blockIdx.x * 4 + warp;
    const int b = lane;
    const float* h1 = g_hbuf[hb] + BVAL * HVAL;

    float acc = 0.f;
    for (int k0 = 0; k0 < 2 * HVAL; k0 += 128) {
#pragma unroll
        for (int it = 0; it < 8; ++it) {
            int flat = tid + it * 128;
            int bb = flat >> 5, kq = flat & 31;
            int k = k0 + kq * 4;
            const float* src = (k < HVAL) ? (g_ctx + bb * HVAL + k)
                                          : (h1 + bb * HVAL + (k - HVAL));
            float4 v = *(const float4*)src;
            c_s[bb][kq * 4 + 0] = v.x; c_s[bb][kq * 4 + 1] = v.y;
            c_s[bb][kq * 4 + 2] = v.z; c_s[bb][kq * 4 + 3] = v.w;
        }
        {
            int r = tid >> 5, kq = tid & 31;
            float4 w = *(const float4*)(Wc + ((size_t)(blockIdx.x * 4 + r)) * 2 * HVAL + k0 + kq * 4);
            w_s[r][kq * 4 + 0] = w.x; w_s[r][kq * 4 + 1] = w.y;
            w_s[r][kq * 4 + 2] = w.z; w_s[r][kq * 4 + 3] = w.w;
        }
        __syncthreads();
#pragma unroll 4
        for (int k = 0; k < 128; k++)
            acc = fmaf(w_s[warp][k], c_s[b][k], acc);
        __syncthreads();
    }
    g_concats[((size_t)(t * BVAL + b)) * HVAL + j] = tanhf(acc + bc[j]);
}

// ---------------- launcher ----------------
extern "C" void kernel_launch(void* const* d_in, const int* in_sizes, int n_in,
                              void* d_out, int out_size) {
    const int* tgt            = (const int*)d_in[0];
    const float* dh           = (const float*)d_in[1];
    const float* enc          = (const float*)d_in[2];
    const unsigned char* mask = (const unsigned char*)d_in[3];
    const float* emb          = (const float*)d_in[4];
    const float* Wih          = (const float*)d_in[5];
    const float* Whh          = (const float*)d_in[6];
    const float* bih          = (const float*)d_in[7];
    const float* bhh          = (const float*)d_in[8];
    const float* Wa           = (const float*)d_in[9];
    const float* ba           = (const float*)d_in[10];
    const float* Wc           = (const float*)d_in[11];
    const float* bc           = (const float*)d_in[12];
    const float* Ws           = (const float*)d_in[13];
    const float* bs           = (const float*)d_in[14];
    float* out = (float*)d_out;

    init_h_kernel<<<(LVAL * BVAL * HVAL + 255) / 256, 256>>>(dh);
    embed_kernel<<<TVAL * BVAL, 128>>>(tgt, emb);

    // enc_proj = enc @ Wa^T + ba   (M=4096, N=512, K=512)
    sgemm_f2_kernel<<<dim3((SVAL * BVAL) / 128, HVAL / 128), 256>>>(
        enc, Wa, ba, nullptr, SVAL * BVAL, HVAL, HVAL, 0, 1);

    // gx0 = x_all @ Wih0^T + bih0  (M=1024, N=1536, K=512)
    sgemm_f2_kernel<<<dim3((TVAL * BVAL) / 128, (3 * HVAL) / 128), 256>>>(
        nullptr, Wih, bih, nullptr, TVAL * BVAL, 3 * HVAL, EVAL, 1, 2);

    // recurrence
    for (int t = 0; t < TVAL; t++) {
        int bin = t & 1, bout = (t + 1) & 1;
        gru_step_kernel<false><<<128, 128>>>(nullptr, Whh, nullptr, bhh, t, 0, bin, bout);
        gru_step_kernel<true><<<128, 128>>>(Wih + 3 * HVAL * EVAL, Whh + 3 * HVAL * HVAL,
                                            bih + 3 * HVAL, bhh + 3 * HVAL, t, 1, bin, bout);
        attn_kernel<<<BVAL, 128>>>(enc, mask, bout);
        concat_kernel<<<128, 128>>>(Wc, bc, t, bout);
    }

    // decoder_outputs = concats @ Ws^T + bs  (M=1024, N=50257, K=512)
    sgemm_f2_kernel<<<dim3((TVAL * BVAL) / 128, (VVAL + 127) / 128), 256>>>(
        nullptr, Ws, bs, out, TVAL * BVAL, VVAL, HVAL, 2, 0);

    // h_final tail
    long main_elems = (long)TVAL * BVAL * VVAL;
    if ((long)out_size >= main_elems + (long)LVAL * BVAL * HVAL)
        final_h_kernel<<<128, 256>>>(out + main_elems);
}

// round 9
// speedup vs baseline: 1.1946x; 1.1946x over previous
#include <cuda_runtime.h>
#include <cuda_bf16.h>
#include <cuda_fp16.h>
#include <math.h>

#define BVAL 32
#define TVAL 32
#define SVAL 128
#define HVAL 512
#define EVAL 512
#define VVAL 50257
#define LVAL 2
#define SOS_ID 1
#define STAGES 3
#define NCTA_REC 128

// ---------------- scratch (device globals; no runtime allocation) ----------------
__device__ float g_encproj[SVAL * BVAL * HVAL];
__device__ float g_xall[TVAL * BVAL * EVAL];
__device__ float g_gx0[TVAL * BVAL * 3 * HVAL];
__device__ float g_hbuf[2][LVAL * BVAL * HVAL];
__device__ float g_ctx[BVAL * HVAL];
__device__ float g_concats[TVAL * BVAL * HVAL];
__device__ unsigned short g_Asplit[4096 * 1536];          // split A (bf16x3 or fp16x2)
__device__ unsigned short g_Bsplit[(size_t)VVAL * 1024];  // split B (max: V rows fp16x2)
__device__ unsigned g_bar_count = 0;
__device__ volatile unsigned g_bar_gen = 0;

__device__ __forceinline__ unsigned smem_u32(const void* p) {
    unsigned a;
    asm("{ .reg .u64 t; cvta.to.shared.u64 t, %1; cvt.u32.u64 %0, t; }" : "=r"(a) : "l"(p));
    return a;
}
__device__ __forceinline__ unsigned swz_off(int row, int chunk) {
    return (unsigned)(row * 64 + ((chunk ^ ((row >> 1) & 3)) << 4));
}

#define LDSM4(R0,R1,R2,R3,ADDR) \
    asm volatile("ldmatrix.sync.aligned.m8n8.x4.shared.b16 {%0,%1,%2,%3}, [%4];" \
        : "=r"(R0),"=r"(R1),"=r"(R2),"=r"(R3) : "r"(ADDR))
#define MMA_BF16(D,A0,A1,A2,A3,B0,B1) \
    asm volatile("mma.sync.aligned.m16n8k16.row.col.f32.bf16.bf16.f32 " \
        "{%0,%1,%2,%3}, {%4,%5,%6,%7}, {%8,%9}, {%0,%1,%2,%3};" \
        : "+f"(D[0]),"+f"(D[1]),"+f"(D[2]),"+f"(D[3]) \
        : "r"(A0),"r"(A1),"r"(A2),"r"(A3),"r"(B0),"r"(B1))
#define MMA_F16(D,A0,A1,A2,A3,B0,B1) \
    asm volatile("mma.sync.aligned.m16n8k16.row.col.f32.f16.f16.f32 " \
        "{%0,%1,%2,%3}, {%4,%5,%6,%7}, {%8,%9}, {%0,%1,%2,%3};" \
        : "+f"(D[0]),"+f"(D[1]),"+f"(D[2]),"+f"(D[3]) \
        : "r"(A0),"r"(A1),"r"(A2),"r"(A3),"r"(B0),"r"(B1))
#define CP_ASYNC16(DST,SRC) \
    asm volatile("cp.async.cg.shared.global [%0], [%1], 16;" :: "r"(DST), "l"(SRC) : "memory")
#define CP_ASYNC16_Z(DST,SRC,SZ) \
    asm volatile("cp.async.cg.shared.global [%0], [%1], 16, %2;" :: "r"(DST), "l"(SRC), "r"(SZ) : "memory")

// ---------------- small kernels ----------------
__global__ void init_h_kernel(const float* __restrict__ dh) {
    int i = blockIdx.x * blockDim.x + threadIdx.x;
    if (i < LVAL * BVAL * HVAL) g_hbuf[0][i] = dh[i];
}
__global__ void final_h_kernel(float* __restrict__ out) {
    int i = blockIdx.x * blockDim.x + threadIdx.x;
    if (i < LVAL * BVAL * HVAL) out[i] = g_hbuf[0][i];
}
__global__ void embed_kernel(const int* __restrict__ tgt, const float* __restrict__ emb) {
    int row = blockIdx.x;
    int t = row >> 5, b = row & 31;
    int tok = (t == 0) ? SOS_ID : tgt[b * TVAL + t - 1];
    float4 v = *(const float4*)(emb + (size_t)tok * EVAL + threadIdx.x * 4);
    *(float4*)(g_xall + (size_t)row * EVAL + threadIdx.x * 4) = v;
}

// ---------------- splits ----------------
__device__ __forceinline__ unsigned short f2bf(float w) {
    __nv_bfloat16 h = __float2bfloat16(w);
    return *(unsigned short*)&h;
}
// bf16x3 A: [hi|lo|hi] stride 1536. a_sel: 0=param, 1=g_xall
__global__ void convertA_bf16(const float* __restrict__ Ap, int a_sel, int M) {
    const float* A = (a_sel == 0) ? Ap : g_xall;
    int i = blockIdx.x * 256 + threadIdx.x;
    if (i >= M * 512) return;
    int m = i >> 9, k = i & 511;
    float w = A[i];
    __nv_bfloat16 hi = __float2bfloat16(w);
    unsigned short lo = f2bf(w - __bfloat162float(hi));
    unsigned short hu = *(unsigned short*)&hi;
    unsigned short* dst = g_Asplit + (size_t)m * 1536;
    dst[k] = hu; dst[512 + k] = lo; dst[1024 + k] = hu;
}
// bf16x3 B: [hi|hi|lo] stride 1536
__global__ void convertB_bf16(const float* __restrict__ W, int N) {
    int i = blockIdx.x * 256 + threadIdx.x;
    if (i >= N * 512) return;
    int n = i >> 9, k = i & 511;
    float w = W[i];
    __nv_bfloat16 hi = __float2bfloat16(w);
    unsigned short lo = f2bf(w - __bfloat162float(hi));
    unsigned short hu = *(unsigned short*)&hi;
    unsigned short* dst = g_Bsplit + (size_t)n * 1536;
    dst[k] = hu; dst[512 + k] = hu; dst[1024 + k] = lo;
}
// fp16x2 A: [hi|lo] stride 1024, from g_concats
__global__ void convertA_f16(int M) {
    int i = blockIdx.x * 256 + threadIdx.x;
    if (i >= M * 512) return;
    int m = i >> 9, k = i & 511;
    float w = g_concats[i];
    __half hi = __float2half_rn(w);
    __half lo = __float2half_rn(w - __half2float(hi));
    unsigned short* dst = g_Asplit + (size_t)m * 1024;
    dst[k] = *(unsigned short*)&hi; dst[512 + k] = *(unsigned short*)&lo;
}
// fp16x2 B: [hi|hi] stride 1024
__global__ void convertB_f16(const float* __restrict__ W, int N) {
    int i = blockIdx.x * 256 + threadIdx.x;
    if (i >= N * 512) return;
    int n = i >> 9, k = i & 511;
    __half hi = __float2half_rn(W[i]);
    unsigned short hu = *(unsigned short*)&hi;
    unsigned short* dst = g_Bsplit + (size_t)n * 1024;
    dst[k] = hu; dst[512 + k] = hu;
}

// ---------------- tensor-core GEMM (R5-proven structure, templated on K') ----------
__device__ __forceinline__ void ld_tile_async(unsigned sbase, int st, int kc,
                                              int m0, int n0, int N, int KS, int tid)
{
    const unsigned abuf = sbase + (unsigned)st * 16384u;
    const unsigned bbuf = abuf + 8192u;
    const int r0 = tid >> 2, cg = tid & 3;
    const int koff = kc * 32 + cg * 8;
#pragma unroll
    for (int h = 0; h < 2; h++) {
        const int row = r0 + h * 64;
        const unsigned off = swz_off(row, cg);
        const unsigned short* sa = g_Asplit + (size_t)(m0 + row) * KS + koff;
        CP_ASYNC16(abuf + off, __cvta_generic_to_global(sa));
        const int brow = n0 + row;
        const unsigned short* sb = g_Bsplit + (size_t)(brow < N ? brow : 0) * KS + koff;
        CP_ASYNC16_Z(bbuf + off, __cvta_generic_to_global(sb), (brow < N) ? 16 : 0);
    }
}

template <int KS, bool FP16>
__global__ __launch_bounds__(256, 2) void bgemm_kernel(
    const float* __restrict__ bias, float* __restrict__ Cp,
    int M, int N, int c_sel)
{
    float* C = (c_sel == 0) ? Cp : (c_sel == 1) ? g_encproj : g_gx0;
    constexpr int NKT = KS / 32;

    __shared__ __align__(16) char smem[STAGES * 16384];
    const unsigned sbase = smem_u32(smem);

    const int tid = threadIdx.x;
    const int warp = tid >> 5, lane = tid & 31;
    const int m0 = blockIdx.x * 128;        // M fastest
    const int n0 = blockIdx.y * 128;
    const int wm = (warp & 3) * 32;
    const int wn = (warp >> 2) * 64;

    const int q = lane >> 3;
    const int rin = lane & 7;
    const int cq = q >> 1;
    unsigned relA[2][2], relB[4][2];
#pragma unroll
    for (int mm = 0; mm < 2; mm++) {
        int row = wm + mm * 16 + ((q & 1) << 3) + rin;
        int rsw = (row >> 1) & 3;
#pragma unroll
        for (int kk = 0; kk < 2; kk++)
            relA[mm][kk] = (unsigned)(row * 64 + (((kk * 2 + cq) ^ rsw) << 4));
    }
#pragma unroll
    for (int nh = 0; nh < 4; nh++) {
        int row = wn + nh * 16 + ((q & 1) << 3) + rin;
        int rsw = (row >> 1) & 3;
#pragma unroll
        for (int kk = 0; kk < 2; kk++)
            relB[nh][kk] = (unsigned)(row * 64 + (((kk * 2 + cq) ^ rsw) << 4));
    }

    float acc[2][8][4];
#pragma unroll
    for (int i = 0; i < 2; i++)
#pragma unroll
        for (int j = 0; j < 8; j++)
#pragma unroll
            for (int c = 0; c < 4; c++) acc[i][j][c] = 0.f;

#pragma unroll
    for (int s = 0; s < STAGES - 1; s++) {
        ld_tile_async(sbase, s, s, m0, n0, N, KS, tid);
        asm volatile("cp.async.commit_group;" ::: "memory");
    }

    for (int kt = 0; kt < NKT; kt++) {
        if (kt == NKT - 1) asm volatile("cp.async.wait_group 0;" ::: "memory");
        else               asm volatile("cp.async.wait_group 1;" ::: "memory");
        __syncthreads();

        const int nl = kt + STAGES - 1;
        if (nl < NKT) {
            ld_tile_async(sbase, nl % STAGES, nl, m0, n0, N, KS, tid);
            asm volatile("cp.async.commit_group;" ::: "memory");
        }

        const unsigned bA = sbase + (unsigned)(kt % STAGES) * 16384u;
        const unsigned bB = bA + 8192u;
#pragma unroll
        for (int kk = 0; kk < 2; kk++) {
            unsigned ra[2][4];
            LDSM4(ra[0][0], ra[0][1], ra[0][2], ra[0][3], bA + relA[0][kk]);
            LDSM4(ra[1][0], ra[1][1], ra[1][2], ra[1][3], bA + relA[1][kk]);
#pragma unroll
            for (int nh = 0; nh < 4; nh++) {
                unsigned rb0, rb1, rb2, rb3;
                LDSM4(rb0, rb1, rb2, rb3, bB + relB[nh][kk]);
                if (FP16) {
                    MMA_F16(acc[0][2 * nh],     ra[0][0], ra[0][1], ra[0][2], ra[0][3], rb0, rb2);
                    MMA_F16(acc[1][2 * nh],     ra[1][0], ra[1][1], ra[1][2], ra[1][3], rb0, rb2);
                    MMA_F16(acc[0][2 * nh + 1], ra[0][0], ra[0][1], ra[0][2], ra[0][3], rb1, rb3);
                    MMA_F16(acc[1][2 * nh + 1], ra[1][0], ra[1][1], ra[1][2], ra[1][3], rb1, rb3);
                } else {
                    MMA_BF16(acc[0][2 * nh],     ra[0][0], ra[0][1], ra[0][2], ra[0][3], rb0, rb2);
                    MMA_BF16(acc[1][2 * nh],     ra[1][0], ra[1][1], ra[1][2], ra[1][3], rb0, rb2);
                    MMA_BF16(acc[0][2 * nh + 1], ra[0][0], ra[0][1], ra[0][2], ra[0][3], rb1, rb3);
                    MMA_BF16(acc[1][2 * nh + 1], ra[1][0], ra[1][1], ra[1][2], ra[1][3], rb1, rb3);
                }
            }
        }
        __syncthreads();
    }

    const int trow = lane >> 2;
    const int tcol = (lane & 3) * 2;
#pragma unroll
    for (int mm = 0; mm < 2; mm++) {
#pragma unroll
        for (int nn = 0; nn < 8; nn++) {
            int r = m0 + wm + mm * 16 + trow;
            int cb = n0 + wn + nn * 8 + tcol;
            float* cr0 = C + (size_t)r * N;
            float* cr1 = C + (size_t)(r + 8) * N;
            if (cb < N) {
                cr0[cb] = acc[mm][nn][0] + bias[cb];
                cr1[cb] = acc[mm][nn][2] + bias[cb];
            }
            if (cb + 1 < N) {
                cr0[cb + 1] = acc[mm][nn][1] + bias[cb + 1];
                cr1[cb + 1] = acc[mm][nn][3] + bias[cb + 1];
            }
        }
    }
}

// ---------------- persistent recurrence: grid barrier ----------------
__device__ __forceinline__ void grid_barrier() {
    __syncthreads();
    if (threadIdx.x == 0) {
        __threadfence();
        unsigned gen = g_bar_gen;
        if (atomicAdd(&g_bar_count, 1u) == (unsigned)(NCTA_REC - 1)) {
            g_bar_count = 0u;
            __threadfence();
            g_bar_gen = gen + 1u;
        } else {
            while (g_bar_gen == gen) { }
        }
        __threadfence();
    }
    __syncthreads();
}

// ---------------- phase bodies (R1-proven, smem remapped onto arena) ----------------
template <bool HAS_X>
__device__ void gru_phase(char* arena,
    const float* __restrict__ Wih, const float* __restrict__ Whh,
    const float* __restrict__ bih, const float* __restrict__ bhh,
    int t, int layer, int buf_in, int buf_out, int cta)
{
    constexpr int PER = HAS_X ? 6 : 3;
    float (*h_s)[133] = (float(*)[133])arena;
    float (*x_s)[133] = (float(*)[133])(arena + 17024);
    float (*w_s)[128] = (float(*)[128])(arena + 34048);

    const int tid = threadIdx.x;
    const int warp = tid >> 5, lane = tid & 31;
    const int j = cta * 4 + warp;
    const int b = lane;

    const float* h_in = g_hbuf[buf_in] + layer * BVAL * HVAL;
    const float* x_in = g_hbuf[buf_out];
    float* h_out = g_hbuf[buf_out] + layer * BVAL * HVAL;

    float ar = 0.f, az = 0.f, an = 0.f;
    float xr = 0.f, xz = 0.f, xn = 0.f;

    for (int k0 = 0; k0 < HVAL; k0 += 128) {
#pragma unroll
        for (int it = 0; it < 8; ++it) {
            int flat = tid + it * 128;
            int bb = flat >> 5, kq = flat & 31;
            float4 v = *(const float4*)(h_in + bb * HVAL + k0 + kq * 4);
            h_s[bb][kq * 4 + 0] = v.x; h_s[bb][kq * 4 + 1] = v.y;
            h_s[bb][kq * 4 + 2] = v.z; h_s[bb][kq * 4 + 3] = v.w;
            if (HAS_X) {
                float4 u = *(const float4*)(x_in + bb * HVAL + k0 + kq * 4);
                x_s[bb][kq * 4 + 0] = u.x; x_s[bb][kq * 4 + 1] = u.y;
                x_s[bb][kq * 4 + 2] = u.z; x_s[bb][kq * 4 + 3] = u.w;
            }
        }
#pragma unroll
        for (int it = 0; it < PER; ++it) {
            int flat = tid + it * 128;
            int r = flat >> 5, kq = flat & 31;
            int jl = r / PER, which = r % PER;
            int jj = cta * 4 + jl;
            const float* src;
            if (HAS_X)
                src = (which < 3) ? (Wih + ((size_t)(which * HVAL + jj)) * HVAL)
                                  : (Whh + ((size_t)((which - 3) * HVAL + jj)) * HVAL);
            else
                src = Whh + ((size_t)(which * HVAL + jj)) * HVAL;
            float4 w = *(const float4*)(src + k0 + kq * 4);
            w_s[r][kq * 4 + 0] = w.x; w_s[r][kq * 4 + 1] = w.y;
            w_s[r][kq * 4 + 2] = w.z; w_s[r][kq * 4 + 3] = w.w;
        }
        __syncthreads();
        const int wb = warp * PER;
#pragma unroll 4
        for (int k = 0; k < 128; k++) {
            float hv = h_s[b][k];
            if (HAS_X) {
                float xv = x_s[b][k];
                xr = fmaf(w_s[wb + 0][k], xv, xr);
                xz = fmaf(w_s[wb + 1][k], xv, xz);
                xn = fmaf(w_s[wb + 2][k], xv, xn);
                ar = fmaf(w_s[wb + 3][k], hv, ar);
                az = fmaf(w_s[wb + 4][k], hv, az);
                an = fmaf(w_s[wb + 5][k], hv, an);
            } else {
                ar = fmaf(w_s[wb + 0][k], hv, ar);
                az = fmaf(w_s[wb + 1][k], hv, az);
                an = fmaf(w_s[wb + 2][k], hv, an);
            }
        }
        __syncthreads();
    }

    float gxr, gxz, gxn;
    if (HAS_X) {
        gxr = xr + bih[j]; gxz = xz + bih[HVAL + j]; gxn = xn + bih[2 * HVAL + j];
    } else {
        const float* g = g_gx0 + ((size_t)(t * BVAL + b)) * 3 * HVAL;
        gxr = g[j]; gxz = g[HVAL + j]; gxn = g[2 * HVAL + j];
    }
    float ghr = ar + bhh[j];
    float ghz = az + bhh[HVAL + j];
    float ghn = an + bhh[2 * HVAL + j];
    float rg = 1.f / (1.f + __expf(-(gxr + ghr)));
    float zg = 1.f / (1.f + __expf(-(gxz + ghz)));
    float ng = tanhf(gxn + rg * ghn);
    h_out[b * HVAL + j] = (1.f - zg) * ng + zg * h_in[b * HVAL + j];
}

__device__ void attn_phase(char* arena, const float* __restrict__ enc,
                           const unsigned char* __restrict__ mask, int hb, int b)
{
    const int tid = threadIdx.x;
    const int warp = tid >> 5, lane = tid & 31;
    const float* h1 = g_hbuf[hb] + BVAL * HVAL;

    float* hs = (float*)arena;               // 512
    float* sc = (float*)(arena + 2048);      // 128
    float* red = (float*)(arena + 2560);     // 4

    ((float4*)hs)[tid] = *(const float4*)(h1 + b * HVAL + tid * 4);
    __syncthreads();

    for (int s = warp; s < SVAL; s += 4) {
        const float* ep = g_encproj + ((size_t)(s * BVAL + b)) * HVAL;
        float p = 0.f;
#pragma unroll 4
        for (int k = lane; k < HVAL; k += 32) p = fmaf(hs[k], ep[k], p);
#pragma unroll
        for (int o = 16; o > 0; o >>= 1) p += __shfl_down_sync(0xffffffffu, p, o);
        if (lane == 0) sc[s] = mask[b * SVAL + s] ? -1e9f : p;
    }
    __syncthreads();

    float v = sc[tid];
    float m = v;
#pragma unroll
    for (int o = 16; o > 0; o >>= 1) m = fmaxf(m, __shfl_xor_sync(0xffffffffu, m, o));
    if (lane == 0) red[warp] = m;
    __syncthreads();
    m = fmaxf(fmaxf(red[0], red[1]), fmaxf(red[2], red[3]));
    __syncthreads();
    float e = __expf(v - m);
    float s = e;
#pragma unroll
    for (int o = 16; o > 0; o >>= 1) s += __shfl_xor_sync(0xffffffffu, s, o);
    if (lane == 0) red[warp] = s;
    __syncthreads();
    s = red[0] + red[1] + red[2] + red[3];
    sc[tid] = e / s;
    __syncthreads();

    for (int hh = tid; hh < HVAL; hh += 128) {
        float acc = 0.f;
#pragma unroll 4
        for (int ss = 0; ss < SVAL; ss++)
            acc = fmaf(sc[ss], enc[((size_t)(ss * BVAL + b)) * HVAL + hh], acc);
        g_ctx[b * HVAL + hh] = acc;
    }
}

__device__ void concat_phase(char* arena, const float* __restrict__ Wc,
                             const float* __restrict__ bc, int t, int hb, int cta)
{
    float (*c_s)[133] = (float(*)[133])arena;
    float (*w_s)[128] = (float(*)[128])(arena + 17024);
    const int tid = threadIdx.x;
    const int warp = tid >> 5, lane = tid & 31;
    const int j = cta * 4 + warp;
    const int b = lane;
    const float* h1 = g_hbuf[hb] + BVAL * HVAL;

    float acc = 0.f;
    for (int k0 = 0; k0 < 2 * HVAL; k0 += 128) {
#pragma unroll
        for (int it = 0; it < 8; ++it) {
            int flat = tid + it * 128;
            int bb = flat >> 5, kq = flat & 31;
            int k = k0 + kq * 4;
            const float* src = (k < HVAL) ? (g_ctx + bb * HVAL + k)
                                          : (h1 + bb * HVAL + (k - HVAL));
            float4 v = *(const float4*)src;
            c_s[bb][kq * 4 + 0] = v.x; c_s[bb][kq * 4 + 1] = v.y;
            c_s[bb][kq * 4 + 2] = v.z; c_s[bb][kq * 4 + 3] = v.w;
        }
        {
            int r = tid >> 5, kq = tid & 31;
            float4 w = *(const float4*)(Wc + ((size_t)(cta * 4 + r)) * 2 * HVAL + k0 + kq * 4);
            w_s[r][kq * 4 + 0] = w.x; w_s[r][kq * 4 + 1] = w.y;
            w_s[r][kq * 4 + 2] = w.z; w_s[r][kq * 4 + 3] = w.w;
        }
        __syncthreads();
#pragma unroll 4
        for (int k = 0; k < 128; k++)
            acc = fmaf(w_s[warp][k], c_s[b][k], acc);
        __syncthreads();
    }
    g_concats[((size_t)(t * BVAL + b)) * HVAL + j] = tanhf(acc + bc[j]);
}

// ---------------- persistent recurrence kernel ----------------
__global__ __launch_bounds__(128) void recurrence_kernel(
    const float* __restrict__ Wih, const float* __restrict__ Whh,
    const float* __restrict__ bih, const float* __restrict__ bhh,
    const float* __restrict__ Wc, const float* __restrict__ bc,
    const float* __restrict__ enc, const unsigned char* __restrict__ mask)
{
    __shared__ __align__(16) char arena[46336];
    const int cta = blockIdx.x;

    for (int t = 0; t < TVAL; t++) {
        const int bin = t & 1, bout = (t + 1) & 1;
        gru_phase<false>(arena, nullptr, Whh, nullptr, bhh, t, 0, bin, bout, cta);
        grid_barrier();
        gru_phase<true>(arena, Wih + 3 * HVAL * EVAL, Whh + 3 * HVAL * HVAL,
                        bih + 3 * HVAL, bhh + 3 * HVAL, t, 1, bin, bout, cta);
        grid_barrier();
        if (cta < BVAL) attn_phase(arena, enc, mask, bout, cta);
        grid_barrier();
        concat_phase(arena, Wc, bc, t, bout, cta);
        // no barrier needed: next gru0 touches only buffers concat doesn't read,
        // and the post-gru0 barrier orders concat before attn(t+1)'s g_ctx writes.
    }
}

// ---------------- launcher ----------------
extern "C" void kernel_launch(void* const* d_in, const int* in_sizes, int n_in,
                              void* d_out, int out_size) {
    const int* tgt            = (const int*)d_in[0];
    const float* dh           = (const float*)d_in[1];
    const float* enc          = (const float*)d_in[2];
    const unsigned char* mask = (const unsigned char*)d_in[3];
    const float* emb          = (const float*)d_in[4];
    const float* Wih          = (const float*)d_in[5];
    const float* Whh          = (const float*)d_in[6];
    const float* bih          = (const float*)d_in[7];
    const float* bhh          = (const float*)d_in[8];
    const float* Wa           = (const float*)d_in[9];
    const float* ba           = (const float*)d_in[10];
    const float* Wc           = (const float*)d_in[11];
    const float* bc           = (const float*)d_in[12];
    const float* Ws           = (const float*)d_in[13];
    const float* bs           = (const float*)d_in[14];
    float* out = (float*)d_out;

    init_h_kernel<<<(LVAL * BVAL * HVAL + 255) / 256, 256>>>(dh);
    embed_kernel<<<TVAL * BVAL, 128>>>(tgt, emb);

    // enc_proj = enc @ Wa^T + ba   (bf16x3, M=4096, N=512)
    convertB_bf16<<<(HVAL * 512 + 255) / 256, 256>>>(Wa, HVAL);
    convertA_bf16<<<(4096 * 512 + 255) / 256, 256>>>(enc, 0, SVAL * BVAL);
    bgemm_kernel<1536, false><<<dim3(32, 4), 256>>>(ba, nullptr, SVAL * BVAL, HVAL, 1);

    // gx0 = x_all @ Wih0^T + bih0  (bf16x3, M=1024, N=1536)
    convertB_bf16<<<(3 * HVAL * 512 + 255) / 256, 256>>>(Wih, 3 * HVAL);
    convertA_bf16<<<(1024 * 512 + 255) / 256, 256>>>(nullptr, 1, TVAL * BVAL);
    bgemm_kernel<1536, false><<<dim3(8, 12), 256>>>(bih, nullptr, TVAL * BVAL, 3 * HVAL, 2);

    // Ws split (fp16x2) before recurrence — g_Bsplit free after gx0 gemm
    convertB_f16<<<(VVAL * 512 + 255) / 256, 256>>>(Ws, VVAL);

    // full recurrence in ONE persistent kernel (128 co-resident CTAs, 3 grid bars/step)
    recurrence_kernel<<<NCTA_REC, 128>>>(Wih, Whh, bih, bhh, Wc, bc, enc, mask);

    // decoder_outputs = concats @ Ws^T + bs  (fp16x2, M=1024, N=50257)
    convertA_f16<<<(1024 * 512 + 255) / 256, 256>>>(TVAL * BVAL);
    bgemm_kernel<1024, true><<<dim3(8, (VVAL + 127) / 128), 256>>>(
        bs, out, TVAL * BVAL, VVAL, 0);

    long main_elems = (long)TVAL * BVAL * VVAL;
    if ((long)out_size >= main_elems + (long)LVAL * BVAL * HVAL)
        final_h_kernel<<<128, 256>>>(out + main_elems);
}